// round 5
// baseline (speedup 1.0000x reference)
#include <cuda_runtime.h>
#include <math.h>

// Problem constants (fixed shapes per setup_inputs)
#define B_    16
#define C_    64
#define HW    441
#define NCLS  10
#define M_    2205
#define MP    2304        // M padded to multiple of BM (18*128)
#define ROWS  7056        // B_*HW
#define ROWSP 7104        // padded to multiple of BQ (111*64)
#define BQ    64          // row tile
#define BM    128         // col (m) tile

// Scratch (device globals — no allocation allowed)
__device__ float g_qn[ROWSP * C_];          // normalized queries, row-major [row][c]
__device__ float g_sn[NCLS * C_ * MP];      // normalized support,  [n][c][m] m-contig
__device__ float g_rowsum[NCLS * ROWS];     // per-(n,row) top3 sum

typedef unsigned long long u64;

__device__ __forceinline__ u64 splat2(float x){
    u64 r; asm("mov.b64 %0, {%1, %1};" : "=l"(r) : "f"(x)); return r;
}
__device__ __forceinline__ u64 fma2(u64 a, u64 b, u64 c){
    u64 d; asm("fma.rn.f32x2 %0, %1, %2, %3;" : "=l"(d) : "l"(a), "l"(b), "l"(c)); return d;
}
__device__ __forceinline__ void unpack2(u64 v, float& lo, float& hi){
    asm("mov.b64 {%0, %1}, %2;" : "=f"(lo), "=f"(hi) : "l"(v));
}

// Branchless sorted top-3 insert: (a>=b>=c) stays sorted after inserting v.
__device__ __forceinline__ void ins3(float v, float& a, float& b, float& c){
    float na = fmaxf(a, v);
    float nb = fmaxf(b, fminf(a, v));
    float nc = fmaxf(c, fminf(b, v));
    a = na; b = nb; c = nc;
}

// ---------------------------------------------------------------------------
// Normalize queries: x1 [B][C][HW] -> g_qn [ROWSP][C], L2 over C per (b,hw).
// Rows >= ROWS zero-filled so the GEMM needs no row guard.
// ---------------------------------------------------------------------------
__global__ void norm_q_kernel(const float* __restrict__ x1){
    int idx = blockIdx.x * blockDim.x + threadIdx.x;
    if (idx >= ROWSP) return;
    float* o = g_qn + idx * C_;
    if (idx >= ROWS){
        #pragma unroll
        for (int c = 0; c < C_; c++) o[c] = 0.f;
        return;
    }
    int b  = idx / HW;
    int qi = idx - b * HW;
    const float* p = x1 + (b * C_) * HW + qi;   // stride HW over c (coalesced over qi)
    float v[C_]; float ss = 0.f;
    #pragma unroll
    for (int c = 0; c < C_; c++){ float t = p[c * HW]; v[c] = t; ss += t * t; }
    float inv = 1.f / fmaxf(sqrtf(ss), 1e-12f);
    #pragma unroll
    for (int c = 0; c < C_; c++) o[c] = v[c] * inv;
}

// ---------------------------------------------------------------------------
// Normalize support: x2 [n][C][M] -> g_sn [n][C][MP], L2 over C per (n,m).
// m in [M, MP) zero-filled so the GEMM B-tile loads need no guard.
// ---------------------------------------------------------------------------
__global__ void norm_s_kernel(const float* __restrict__ x2){
    int idx = blockIdx.x * blockDim.x + threadIdx.x;
    if (idx >= NCLS * MP) return;
    int n = idx / MP;
    int m = idx - n * MP;
    float* o = g_sn + n * (C_ * MP) + m;
    if (m >= M_){
        #pragma unroll
        for (int c = 0; c < C_; c++) o[c * MP] = 0.f;
        return;
    }
    const float* p = x2 + n * (C_ * M_) + m;    // stride M_ over c (coalesced over m)
    float v[C_]; float ss = 0.f;
    #pragma unroll
    for (int c = 0; c < C_; c++){ float t = p[c * M_]; v[c] = t; ss += t * t; }
    float inv = 1.f / fmaxf(sqrtf(ss), 1e-12f);
    #pragma unroll
    for (int c = 0; c < C_; c++) o[c * MP] = v[c] * inv;
}

// ---------------------------------------------------------------------------
// Main: fused GEMM + per-row running top-3.
// grid = (ROWSP/BQ = 111, NCLS = 10), block = 256.
// Thread layout: tx = tid&31 -> 32 col-groups of 4 cols (BM=128)
//                ty = tid>>5 ->  8 row-groups of 8 rows (BQ=64)
// A warp shares rows (same ty) -> full-warp shfl_xor merge of top3.
// f32x2: accumulators pair consecutive rows; A pairs load directly from
// k-major shared (no splat), B scalars splatted (4 MOVs per k for 16 FFMA2).
// ---------------------------------------------------------------------------
__global__ void __launch_bounds__(256) sim_topk_kernel(){
    __shared__ float As[C_][BQ];   // [k][row]  16 KB (transposed: row-pairs adjacent)
    __shared__ float Bs[C_][BM];   // [k][m]    32 KB
    const int n    = blockIdx.y;
    const int row0 = blockIdx.x * BQ;
    const int tid  = threadIdx.x;
    const int tx   = tid & 31;
    const int ty   = tid >> 5;

    // Load A tile transposed: g_qn[row0+r][k] -> As[k][r]
    {
        const int r  = tid >> 2;           // 0..63
        const int kq = (tid & 3) << 4;     // 0,16,32,48
        const float* src = g_qn + (row0 + r) * C_ + kq;
        #pragma unroll
        for (int i = 0; i < 4; i++){
            float4 v = *reinterpret_cast<const float4*>(src + i * 4);
            As[kq + i*4 + 0][r] = v.x;
            As[kq + i*4 + 1][r] = v.y;
            As[kq + i*4 + 2][r] = v.z;
            As[kq + i*4 + 3][r] = v.w;
        }
    }

    float t0[8], t1[8], t2[8];
    #pragma unroll
    for (int r = 0; r < 8; r++){ t0[r] = -INFINITY; t1[r] = -INFINITY; t2[r] = -INFINITY; }

    const float* sbase = g_sn + n * (C_ * MP);

    for (int m0 = 0; m0 < M_; m0 += BM){
        __syncthreads();   // protect Bs from prior-iteration readers
        // Load B tile: 64 x 128 floats; 4 threads per k-row, 8 float4 each
        {
            const int k  = tid >> 2;          // 0..63
            const int mq = (tid & 3) << 5;    // 0,32,64,96
            const float* src = sbase + k * MP + m0 + mq;   // always in-bounds (MP pad)
            float* dst = &Bs[k][mq];
            #pragma unroll
            for (int j = 0; j < 8; j++)
                *reinterpret_cast<float4*>(dst + j*4) =
                    *reinterpret_cast<const float4*>(src + j*4);
        }
        __syncthreads();

        u64 acc[4][4];
        #pragma unroll
        for (int rp = 0; rp < 4; rp++)
            #pragma unroll
            for (int c = 0; c < 4; c++) acc[rp][c] = 0ull;

        #pragma unroll 16
        for (int k = 0; k < C_; k++){
            // 8 rows as 4 packed pairs (broadcast across warp: same ty)
            const ulonglong2* ap = reinterpret_cast<const ulonglong2*>(&As[k][ty * 8]);
            ulonglong2 p0 = ap[0];
            ulonglong2 p1 = ap[1];
            // 4 cols, splat each into both f32x2 lanes
            float4 bv = *reinterpret_cast<const float4*>(&Bs[k][tx * 4]);
            u64 b0 = splat2(bv.x), b1 = splat2(bv.y), b2 = splat2(bv.z), b3 = splat2(bv.w);
            acc[0][0]=fma2(p0.x,b0,acc[0][0]); acc[1][0]=fma2(p0.y,b0,acc[1][0]);
            acc[2][0]=fma2(p1.x,b0,acc[2][0]); acc[3][0]=fma2(p1.y,b0,acc[3][0]);
            acc[0][1]=fma2(p0.x,b1,acc[0][1]); acc[1][1]=fma2(p0.y,b1,acc[1][1]);
            acc[2][1]=fma2(p1.x,b1,acc[2][1]); acc[3][1]=fma2(p1.y,b1,acc[3][1]);
            acc[0][2]=fma2(p0.x,b2,acc[0][2]); acc[1][2]=fma2(p0.y,b2,acc[1][2]);
            acc[2][2]=fma2(p1.x,b2,acc[2][2]); acc[3][2]=fma2(p1.y,b2,acc[3][2]);
            acc[0][3]=fma2(p0.x,b3,acc[0][3]); acc[1][3]=fma2(p0.y,b3,acc[1][3]);
            acc[2][3]=fma2(p1.x,b3,acc[2][3]); acc[3][3]=fma2(p1.y,b3,acc[3][3]);
        }

        // Fold this tile's sims into the running top-3 (mask padded cols)
        const int mbase = m0 + tx * 4;
        #pragma unroll
        for (int c = 0; c < 4; c++){
            const bool valid = (mbase + c) < M_;
            #pragma unroll
            for (int rp = 0; rp < 4; rp++){
                float lo, hi; unpack2(acc[rp][c], lo, hi);
                lo = valid ? lo : -INFINITY;
                hi = valid ? hi : -INFINITY;
                ins3(lo, t0[2*rp],   t1[2*rp],   t2[2*rp]);
                ins3(hi, t0[2*rp+1], t1[2*rp+1], t2[2*rp+1]);
            }
        }
    }

    // Merge top-3 across the 32 lanes sharing these rows (butterfly)
    #pragma unroll
    for (int off = 16; off >= 1; off >>= 1){
        #pragma unroll
        for (int r = 0; r < 8; r++){
            float u0 = __shfl_xor_sync(0xffffffffu, t0[r], off);
            float u1 = __shfl_xor_sync(0xffffffffu, t1[r], off);
            float u2 = __shfl_xor_sync(0xffffffffu, t2[r], off);
            ins3(u0, t0[r], t1[r], t2[r]);
            ins3(u1, t0[r], t1[r], t2[r]);
            ins3(u2, t0[r], t1[r], t2[r]);
        }
    }

    if (tx == 0){
        #pragma unroll
        for (int r = 0; r < 8; r++){
            int grow = row0 + ty * 8 + r;
            if (grow < ROWS)
                g_rowsum[n * ROWS + grow] = t0[r] + t1[r] + t2[r];
        }
    }
}

// ---------------------------------------------------------------------------
// out[b][n] = sum over qi of rowsum — deterministic (no float atomics).
// grid = (B_, NCLS), block = 128.
// ---------------------------------------------------------------------------
__global__ void reduce_out_kernel(float* __restrict__ out){
    const int b   = blockIdx.x;
    const int n   = blockIdx.y;
    const int tid = threadIdx.x;
    __shared__ float sh[4];
    float s = 0.f;
    for (int qi = tid; qi < HW; qi += 128)
        s += g_rowsum[n * ROWS + b * HW + qi];
    #pragma unroll
    for (int o = 16; o; o >>= 1) s += __shfl_down_sync(0xffffffffu, s, o);
    if ((tid & 31) == 0) sh[tid >> 5] = s;
    __syncthreads();
    if (tid == 0) out[b * NCLS + n] = sh[0] + sh[1] + sh[2] + sh[3];
}

extern "C" void kernel_launch(void* const* d_in, const int* in_sizes, int n_in,
                              void* d_out, int out_size){
    const float* x1 = (const float*)d_in[0];   // [16,64,21,21] fp32
    const float* x2 = (const float*)d_in[1];   // [10,64,2205]  fp32
    // d_in[2] = neighbor_k (always 3 per setup)
    float* out = (float*)d_out;                // [16,10] fp32

    norm_q_kernel<<<(ROWSP + 255) / 256, 256>>>(x1);
    norm_s_kernel<<<(NCLS * MP + 255) / 256, 256>>>(x2);
    sim_topk_kernel<<<dim3(ROWSP / BQ, NCLS), 256>>>();
    reduce_out_kernel<<<dim3(B_, NCLS), 128>>>(out);
}

// round 9
// speedup vs baseline: 7.2341x; 7.2341x over previous
#include <cuda_runtime.h>
#include <cuda_bf16.h>
#include <math.h>
#include <stdint.h>

// ---------------- problem constants ----------------
#define B_    16
#define C_    64
#define HW    441
#define NCLS  10
#define M_    2205
#define MT    128            // m tile
#define NT    18             // m tiles (18*128 = 2304)
#define MP    2304
#define ROWS  7056
#define RT    128            // row tile
#define RB    56             // row blocks (56*128 = 7168)
#define ROWSP 7168

// ---------------- device scratch (no allocation allowed) ----------------
__device__ __align__(16) __nv_bfloat16 g_qh[ROWSP * C_];       // normalized queries [row][k]
__device__ __align__(16) __nv_bfloat16 g_sh[NCLS * MP * C_];   // normalized support [n][m][k]
__device__ float g_rowsum[NCLS * ROWS];                        // per-(n,row) top3 sum

typedef uint32_t u32;

// ---------------- PTX helpers (all plain-sm_103-safe) ----------------
__device__ __forceinline__ u32 smem_u32(const void* p){
    u32 a;
    asm("{ .reg .u64 t; cvta.to.shared.u64 t, %1; cvt.u32.u64 %0, t; }" : "=r"(a) : "l"(p));
    return a;
}
// Branchless sorted top-3 insert: (a>=b>=c) stays sorted after inserting v.
__device__ __forceinline__ void ins3(float v, float& a, float& b, float& c){
    float na = fmaxf(a, v);
    float nb = fmaxf(b, fminf(a, v));
    float nc = fmaxf(c, fminf(b, v));
    a = na; b = nb; c = nc;
}

#define SW(off) ((u32)(off) ^ (((u32)(off) >> 3) & 0x70u))

#define CPA16(dst, src) \
    asm volatile("cp.async.cg.shared.global [%0], [%1], 16;" :: "r"(dst), "l"(src) : "memory")
#define CPA_COMMIT() asm volatile("cp.async.commit_group;" ::: "memory")

#define LDMX4(r, a) \
    asm volatile("ldmatrix.sync.aligned.m8n8.x4.shared.b16 {%0,%1,%2,%3}, [%4];" \
        : "=r"((r)[0]), "=r"((r)[1]), "=r"((r)[2]), "=r"((r)[3]) : "r"(a))

#define MMA16816(c, a, b0, b1) \
    asm volatile("mma.sync.aligned.m16n8k16.row.col.f32.bf16.bf16.f32 " \
        "{%0,%1,%2,%3}, {%4,%5,%6,%7}, {%8,%9}, {%0,%1,%2,%3};" \
        : "+f"((c)[0]), "+f"((c)[1]), "+f"((c)[2]), "+f"((c)[3]) \
        : "r"((a)[0]), "r"((a)[1]), "r"((a)[2]), "r"((a)[3]), "r"(b0), "r"(b1))

// ---------------------------------------------------------------------------
// Normalize queries: x1 [B][C][HW] -> g_qh [7168][64] bf16, L2 over C.
// ---------------------------------------------------------------------------
__global__ void norm_q_kernel(const float* __restrict__ x1){
    int idx = blockIdx.x * blockDim.x + threadIdx.x;
    if (idx >= ROWSP) return;
    __nv_bfloat162* o = reinterpret_cast<__nv_bfloat162*>(g_qh + (size_t)idx * C_);
    if (idx >= ROWS){
        #pragma unroll
        for (int c = 0; c < C_/2; c++) o[c] = __floats2bfloat162_rn(0.f, 0.f);
        return;
    }
    int b  = idx / HW;
    int qi = idx - b * HW;
    const float* p = x1 + (size_t)b * C_ * HW + qi;
    float v[C_]; float ss = 0.f;
    #pragma unroll
    for (int c = 0; c < C_; c++){ float u = p[c * HW]; v[c] = u; ss += u * u; }
    float inv = 1.f / fmaxf(sqrtf(ss), 1e-12f);
    #pragma unroll
    for (int c = 0; c < C_/2; c++)
        o[c] = __floats2bfloat162_rn(v[2*c] * inv, v[2*c+1] * inv);
}

// ---------------------------------------------------------------------------
// Normalize support: x2 [n][C][M] -> g_sh [n][2304][64] bf16 (k contiguous).
// ---------------------------------------------------------------------------
__global__ void norm_s_kernel(const float* __restrict__ x2){
    int idx = blockIdx.x * blockDim.x + threadIdx.x;
    if (idx >= NCLS * MP) return;
    int n = idx / MP;
    int m = idx - n * MP;
    __nv_bfloat162* o = reinterpret_cast<__nv_bfloat162*>(g_sh + (size_t)idx * C_);
    if (m >= M_){
        #pragma unroll
        for (int c = 0; c < C_/2; c++) o[c] = __floats2bfloat162_rn(0.f, 0.f);
        return;
    }
    const float* p = x2 + (size_t)n * C_ * M_ + m;
    float v[C_]; float ss = 0.f;
    #pragma unroll
    for (int c = 0; c < C_; c++){ float u = p[c * M_]; v[c] = u; ss += u * u; }
    float inv = 1.f / fmaxf(sqrtf(ss), 1e-12f);
    #pragma unroll
    for (int c = 0; c < C_/2; c++)
        o[c] = __floats2bfloat162_rn(v[2*c] * inv, v[2*c+1] * inv);
}

// ---------------------------------------------------------------------------
// Main: mma.sync bf16 GEMM (CTA 128x128, K=64) + fused scalar top-3.
// grid = (56, 10), block = 256 (8 warps). Warp tile 32 rows x 64 cols, in two
// 32-col passes. cp.async double-buffered B tiles; A tile resident.
// smem: [0,16K) A (swizzled) -> reused as merge buf; [16K,32K) B0; [32K,48K) B1.
// mma frag: c[q] -> row = lane>>2 (+8 for q>=2), col = 2*(lane&3) + (q&1).
// Top-3 state per thread: 4 row-slots (mf in 0..1, half in 0..1).
// ---------------------------------------------------------------------------
__global__ void __launch_bounds__(256, 2) sim_mma_kernel(){
    __shared__ __align__(16) char smem[49152];
    const u32 sb   = smem_u32(smem);
    const int tid  = threadIdx.x;
    const int wid  = tid >> 5;
    const int lane = tid & 31;
    const int n    = blockIdx.y;
    const int row0 = blockIdx.x * RT;
    const int mrow = (wid & 3) * 32;          // warp's row offset in tile
    const int ncol = (wid >> 2) * 64;         // warp's col offset in tile

    const char* gA = (const char*)g_qh + (size_t)row0 * C_ * 2;
    const char* gB = (const char*)g_sh + (size_t)n * MP * C_ * 2;

    // Prologue: A + B tile0 (group0), B tile1 (group1). 16KB each = 1024 chunks.
    #pragma unroll
    for (int i = 0; i < 4; i++){
        int j = tid + i * 256;
        CPA16(sb + SW(j * 16), gA + (size_t)j * 16);
    }
    #pragma unroll
    for (int i = 0; i < 4; i++){
        int j = tid + i * 256;
        CPA16(sb + 16384u + SW(j * 16), gB + (size_t)j * 16);
    }
    CPA_COMMIT();
    #pragma unroll
    for (int i = 0; i < 4; i++){
        int j = tid + i * 256;
        CPA16(sb + 32768u + SW(j * 16), gB + 16384 + (size_t)j * 16);
    }
    CPA_COMMIT();

    const int rA    = lane & 15;              // ldmatrix row-within-frag
    const int khalf = (lane >> 4) * 8;        // ldmatrix k-half
    const u32 swx   = (u32)((rA & 7) << 4);   // SW128 xor term (row low bits)

    // Top-3 state: slot s = mf*2 + half; row = mrow + mf*16 + half*8 + (lane>>2)
    float s0[4], s1[4], s2[4];
    #pragma unroll
    for (int s = 0; s < 4; s++){ s0[s] = -INFINITY; s1[s] = -INFINITY; s2[s] = -INFINITY; }

    for (int t = 0; t < NT; t++){
        if (t == NT - 1) asm volatile("cp.async.wait_group 0;" ::: "memory");
        else             asm volatile("cp.async.wait_group 1;" ::: "memory");
        __syncthreads();
        const u32 bbase = sb + ((t & 1) ? 32768u : 16384u);

        #pragma unroll
        for (int pass = 0; pass < 2; pass++){
            float c[2][4][4];
            #pragma unroll
            for (int mf = 0; mf < 2; mf++)
                #pragma unroll
                for (int nf = 0; nf < 4; nf++)
                    #pragma unroll
                    for (int q = 0; q < 4; q++) c[mf][nf][q] = 0.f;

            #pragma unroll
            for (int ks = 0; ks < 4; ks++){
                const u32 colb = ((u32)((ks * 16 + khalf) * 2)) ^ swx;
                u32 a0[4], a1[4], bA[4], bB[4];
                const u32 aaddr = sb + (u32)((mrow + rA) * 128) + colb;
                LDMX4(a0, aaddr);
                LDMX4(a1, aaddr + 2048u);
                const u32 baddr = bbase + (u32)((ncol + pass * 32 + rA) * 128) + colb;
                LDMX4(bA, baddr);
                LDMX4(bB, baddr + 2048u);
                MMA16816(c[0][0], a0, bA[0], bA[2]);
                MMA16816(c[0][1], a0, bA[1], bA[3]);
                MMA16816(c[0][2], a0, bB[0], bB[2]);
                MMA16816(c[0][3], a0, bB[1], bB[3]);
                MMA16816(c[1][0], a1, bA[0], bA[2]);
                MMA16816(c[1][1], a1, bA[1], bA[3]);
                MMA16816(c[1][2], a1, bB[0], bB[2]);
                MMA16816(c[1][3], a1, bB[1], bB[3]);
            }

            // Fold sims into running top-3 (scalar FMNMX; packed min/max has
            // no PTX form on this toolchain).
            if (t < NT - 1){
                #pragma unroll
                for (int mf = 0; mf < 2; mf++)
                    #pragma unroll
                    for (int nf = 0; nf < 4; nf++){
                        ins3(c[mf][nf][0], s0[mf*2],   s1[mf*2],   s2[mf*2]);
                        ins3(c[mf][nf][1], s0[mf*2],   s1[mf*2],   s2[mf*2]);
                        ins3(c[mf][nf][2], s0[mf*2+1], s1[mf*2+1], s2[mf*2+1]);
                        ins3(c[mf][nf][3], s0[mf*2+1], s1[mf*2+1], s2[mf*2+1]);
                    }
            } else {
                const int rem = M_ - (NT - 1) * MT;   // 29 valid cols in last tile
                #pragma unroll
                for (int nf = 0; nf < 4; nf++){
                    const int col0 = ncol + pass * 32 + nf * 8 + (lane & 3) * 2;
                    const bool v0 = col0     < rem;
                    const bool v1 = col0 + 1 < rem;
                    #pragma unroll
                    for (int mf = 0; mf < 2; mf++){
                        ins3(v0 ? c[mf][nf][0] : -INFINITY, s0[mf*2],   s1[mf*2],   s2[mf*2]);
                        ins3(v1 ? c[mf][nf][1] : -INFINITY, s0[mf*2],   s1[mf*2],   s2[mf*2]);
                        ins3(v0 ? c[mf][nf][2] : -INFINITY, s0[mf*2+1], s1[mf*2+1], s2[mf*2+1]);
                        ins3(v1 ? c[mf][nf][3] : -INFINITY, s0[mf*2+1], s1[mf*2+1], s2[mf*2+1]);
                    }
                }
            }
        }
        __syncthreads();
        if (t + 2 < NT){
            const u32 dst = sb + ((t & 1) ? 32768u : 16384u);   // buffer just freed
            #pragma unroll
            for (int i = 0; i < 4; i++){
                int j = tid + i * 256;
                CPA16(dst + SW(j * 16), gB + (size_t)(t + 2) * 16384 + (size_t)j * 16);
            }
            CPA_COMMIT();
        }
    }

    // Merge across the 4 lanes sharing each row (lane groups of 4).
    #pragma unroll
    for (int off = 1; off <= 2; off <<= 1){
        #pragma unroll
        for (int s = 0; s < 4; s++){
            float u0 = __shfl_xor_sync(0xffffffffu, s0[s], off);
            float u1 = __shfl_xor_sync(0xffffffffu, s1[s], off);
            float u2 = __shfl_xor_sync(0xffffffffu, s2[s], off);
            ins3(u0, s0[s], s1[s], s2[s]);
            ins3(u1, s0[s], s1[s], s2[s]);
            ins3(u2, s0[s], s1[s], s2[s]);
        }
    }
    // Merge the two column-half warps via smem (reuse A region) and store.
    float* mrg = reinterpret_cast<float*>(smem);
    if (wid >= 4 && (lane & 3) == 0){
        #pragma unroll
        for (int s = 0; s < 4; s++){
            int row = mrow + (s >> 1) * 16 + (s & 1) * 8 + (lane >> 2);
            mrg[row * 3 + 0] = s0[s];
            mrg[row * 3 + 1] = s1[s];
            mrg[row * 3 + 2] = s2[s];
        }
    }
    __syncthreads();
    if (wid < 4 && (lane & 3) == 0){
        #pragma unroll
        for (int s = 0; s < 4; s++){
            int row = mrow + (s >> 1) * 16 + (s & 1) * 8 + (lane >> 2);
            ins3(mrg[row * 3 + 0], s0[s], s1[s], s2[s]);
            ins3(mrg[row * 3 + 1], s0[s], s1[s], s2[s]);
            ins3(mrg[row * 3 + 2], s0[s], s1[s], s2[s]);
            int grow = row0 + row;
            if (grow < ROWS)
                g_rowsum[n * ROWS + grow] = s0[s] + s1[s] + s2[s];
        }
    }
}

// ---------------------------------------------------------------------------
// out[b][n] = sum over qi of rowsum — deterministic reduction.
// ---------------------------------------------------------------------------
__global__ void reduce_out_kernel(float* __restrict__ out){
    const int b   = blockIdx.x;
    const int n   = blockIdx.y;
    const int tid = threadIdx.x;
    __shared__ float sh[4];
    float s = 0.f;
    for (int qi = tid; qi < HW; qi += 128)
        s += g_rowsum[n * ROWS + b * HW + qi];
    #pragma unroll
    for (int o = 16; o; o >>= 1) s += __shfl_down_sync(0xffffffffu, s, o);
    if ((tid & 31) == 0) sh[tid >> 5] = s;
    __syncthreads();
    if (tid == 0) out[b * NCLS + n] = sh[0] + sh[1] + sh[2] + sh[3];
}

extern "C" void kernel_launch(void* const* d_in, const int* in_sizes, int n_in,
                              void* d_out, int out_size){
    const float* x1 = (const float*)d_in[0];   // [16,64,21,21] fp32
    const float* x2 = (const float*)d_in[1];   // [10,64,2205]  fp32
    float* out = (float*)d_out;                // [16,10] fp32

    norm_q_kernel<<<(ROWSP + 255) / 256, 256>>>(x1);
    norm_s_kernel<<<(NCLS * MP + 255) / 256, 256>>>(x2);
    sim_mma_kernel<<<dim3(RB, NCLS), 256>>>();
    reduce_out_kernel<<<dim3(B_, NCLS), 128>>>(out);
}

// round 11
// speedup vs baseline: 8.9356x; 1.2352x over previous
#include <cuda_runtime.h>
#include <cuda_bf16.h>
#include <math.h>
#include <stdint.h>

// ---------------- problem constants ----------------
#define B_    16
#define C_    64
#define HW    441
#define NCLS  10
#define M_    2205
#define MT    128            // m tile
#define NT    18             // m tiles (18*128 = 2304)
#define MP    2304
#define ROWS  7056
#define RT    128            // row tile
#define RB    56             // row blocks (56*128 = 7168)
#define ROWSP 7168
#define QB    28             // norm blocks for q (28*256 = 7168)
#define SBK   90             // norm blocks for s (90*256 = 23040)

// ---------------- device scratch (no allocation allowed) ----------------
__device__ __align__(16) __nv_bfloat16 g_qh[ROWSP * C_];       // normalized queries [row][k]
__device__ __align__(16) __nv_bfloat16 g_sh[NCLS * MP * C_];   // normalized support [n][m][k]
__device__ float g_part[NCLS * RB * 2];                        // per-(n,block) b-segment sums

typedef uint32_t u32;

// ---------------- PTX helpers (all plain-sm_103-safe) ----------------
__device__ __forceinline__ u32 smem_u32(const void* p){
    u32 a;
    asm("{ .reg .u64 t; cvta.to.shared.u64 t, %1; cvt.u32.u64 %0, t; }" : "=r"(a) : "l"(p));
    return a;
}
// Scalar branchless sorted top-3 insert.
__device__ __forceinline__ void ins3(float v, float& a, float& b, float& c){
    float na = fmaxf(a, v);
    float nb = fmaxf(b, fminf(a, v));
    float nc = fmaxf(c, fminf(b, v));
    a = na; b = nb; c = nc;
}
// Packed bf16x2 top-3 insert: two independent streams per register.
__device__ __forceinline__ void ins3pb(__nv_bfloat162 v, __nv_bfloat162& a,
                                       __nv_bfloat162& b, __nv_bfloat162& c){
    __nv_bfloat162 na = __hmax2(a, v);
    __nv_bfloat162 nb = __hmax2(b, __hmin2(a, v));
    __nv_bfloat162 nc = __hmax2(c, __hmin2(b, v));
    a = na; b = nb; c = nc;
}

#define SW(off) ((u32)(off) ^ (((u32)(off) >> 3) & 0x70u))

#define CPA16(dst, src) \
    asm volatile("cp.async.cg.shared.global [%0], [%1], 16;" :: "r"(dst), "l"(src) : "memory")
#define CPA_COMMIT() asm volatile("cp.async.commit_group;" ::: "memory")

#define LDMX4(r, a) \
    asm volatile("ldmatrix.sync.aligned.m8n8.x4.shared.b16 {%0,%1,%2,%3}, [%4];" \
        : "=r"((r)[0]), "=r"((r)[1]), "=r"((r)[2]), "=r"((r)[3]) : "r"(a))

#define MMA16816(c, a, b0, b1) \
    asm volatile("mma.sync.aligned.m16n8k16.row.col.f32.bf16.bf16.f32 " \
        "{%0,%1,%2,%3}, {%4,%5,%6,%7}, {%8,%9}, {%0,%1,%2,%3};" \
        : "+f"((c)[0]), "+f"((c)[1]), "+f"((c)[2]), "+f"((c)[3]) \
        : "r"((a)[0]), "r"((a)[1]), "r"((a)[2]), "r"((a)[3]), "r"(b0), "r"(b1))

// ---------------------------------------------------------------------------
// Fused normalize: blocks [0,QB) do queries, [QB, QB+SBK) do support.
//   q: x1 [B][C][HW] -> g_qh [7168][64] bf16, L2 over C; pad rows zeroed.
//   s: x2 [n][C][M]  -> g_sh [n][2304][64] bf16 (k contig); pad m zeroed.
// ---------------------------------------------------------------------------
__global__ void norm_kernel(const float* __restrict__ x1, const float* __restrict__ x2){
    if (blockIdx.x < QB){
        int idx = blockIdx.x * 256 + threadIdx.x;          // < 7168 always
        __nv_bfloat162* o = reinterpret_cast<__nv_bfloat162*>(g_qh + (size_t)idx * C_);
        if (idx >= ROWS){
            #pragma unroll
            for (int c = 0; c < C_/2; c++) o[c] = __floats2bfloat162_rn(0.f, 0.f);
            return;
        }
        int b  = idx / HW;
        int qi = idx - b * HW;
        const float* p = x1 + (size_t)b * C_ * HW + qi;
        float v[C_]; float ss = 0.f;
        #pragma unroll
        for (int c = 0; c < C_; c++){ float u = p[c * HW]; v[c] = u; ss += u * u; }
        float inv = 1.f / fmaxf(sqrtf(ss), 1e-12f);
        #pragma unroll
        for (int c = 0; c < C_/2; c++)
            o[c] = __floats2bfloat162_rn(v[2*c] * inv, v[2*c+1] * inv);
    } else {
        int idx = (blockIdx.x - QB) * 256 + threadIdx.x;   // < 23040 always
        int n = idx / MP;
        int m = idx - n * MP;
        __nv_bfloat162* o = reinterpret_cast<__nv_bfloat162*>(g_sh + (size_t)idx * C_);
        if (m >= M_){
            #pragma unroll
            for (int c = 0; c < C_/2; c++) o[c] = __floats2bfloat162_rn(0.f, 0.f);
            return;
        }
        const float* p = x2 + (size_t)n * C_ * M_ + m;
        float v[C_]; float ss = 0.f;
        #pragma unroll
        for (int c = 0; c < C_; c++){ float u = p[c * M_]; v[c] = u; ss += u * u; }
        float inv = 1.f / fmaxf(sqrtf(ss), 1e-12f);
        #pragma unroll
        for (int c = 0; c < C_/2; c++)
            o[c] = __floats2bfloat162_rn(v[2*c] * inv, v[2*c+1] * inv);
    }
}

// ---------------------------------------------------------------------------
// Main: mma.sync bf16 GEMM (CTA 128x128, K=64) + fused packed-bf16 top-3.
// grid = (56, 10), block = 256 (8 warps). Warp tile 32 rows x 64 cols in two
// 32-col passes. cp.async double-buffered B; A tile resident, frags hoisted.
// smem: [0,16K) A (swizzled) -> reused as merge/reduce buf; [16K..48K) B0/B1.
// mma frag: c[q] -> row = lane>>2 (+8 for q>=2), col = 2*(lane&3) + (q&1).
// ---------------------------------------------------------------------------
__global__ void __launch_bounds__(256, 2) sim_mma_kernel(){
    __shared__ __align__(16) char smem[49152];
    const u32 sb   = smem_u32(smem);
    const int tid  = threadIdx.x;
    const int wid  = tid >> 5;
    const int lane = tid & 31;
    const int n    = blockIdx.y;
    const int blk  = blockIdx.x;
    const int row0 = blk * RT;
    const int mrow = (wid & 3) * 32;          // warp's row offset in tile
    const int ncol = (wid >> 2) * 64;         // warp's col offset in tile

    const char* gA = (const char*)g_qh + (size_t)row0 * C_ * 2;
    const char* gB = (const char*)g_sh + (size_t)n * MP * C_ * 2;

    // Prologue: group0 = {A, B0}; group1 = {B1}. 16KB each = 1024 16B chunks.
    #pragma unroll
    for (int i = 0; i < 4; i++){
        int j = tid + i * 256;
        CPA16(sb + SW(j * 16), gA + (size_t)j * 16);
    }
    #pragma unroll
    for (int i = 0; i < 4; i++){
        int j = tid + i * 256;
        CPA16(sb + 16384u + SW(j * 16), gB + (size_t)j * 16);
    }
    CPA_COMMIT();
    #pragma unroll
    for (int i = 0; i < 4; i++){
        int j = tid + i * 256;
        CPA16(sb + 32768u + SW(j * 16), gB + 16384 + (size_t)j * 16);
    }
    CPA_COMMIT();

    const int rA    = lane & 15;              // ldmatrix row-within-frag
    const int khalf = (lane >> 4) * 8;        // ldmatrix k-half
    const u32 swx   = (u32)((rA & 7) << 4);   // SW128 xor term (row low bits)

    // A is tile-loop invariant: hoist all A fragments (32 regs).
    asm volatile("cp.async.wait_group 1;" ::: "memory");
    __syncthreads();
    u32 af[4][8];
    #pragma unroll
    for (int ks = 0; ks < 4; ks++){
        const u32 colb  = ((u32)((ks * 16 + khalf) * 2)) ^ swx;
        const u32 aaddr = sb + (u32)((mrow + rA) * 128) + colb;
        LDMX4(af[ks],     aaddr);
        LDMX4(af[ks] + 4, aaddr + 2048u);
    }

    // Packed top-3 state: slot s = mf*2 + half; two col-streams per slot.
    const __nv_bfloat162 NI2 = __floats2bfloat162_rn(-INFINITY, -INFINITY);
    __nv_bfloat162 p0[4], p1[4], p2[4];
    #pragma unroll
    for (int s = 0; s < 4; s++){ p0[s] = NI2; p1[s] = NI2; p2[s] = NI2; }

    for (int t = 0; t < NT; t++){
        if (t == NT - 1) asm volatile("cp.async.wait_group 0;" ::: "memory");
        else             asm volatile("cp.async.wait_group 1;" ::: "memory");
        __syncthreads();
        const u32 bbase = sb + ((t & 1) ? 32768u : 16384u);

        #pragma unroll
        for (int pass = 0; pass < 2; pass++){
            float c[2][4][4];
            #pragma unroll
            for (int mf = 0; mf < 2; mf++)
                #pragma unroll
                for (int nf = 0; nf < 4; nf++)
                    #pragma unroll
                    for (int q = 0; q < 4; q++) c[mf][nf][q] = 0.f;

            #pragma unroll
            for (int ks = 0; ks < 4; ks++){
                const u32 colb = ((u32)((ks * 16 + khalf) * 2)) ^ swx;
                u32 bA[4], bB[4];
                const u32 baddr = bbase + (u32)((ncol + pass * 32 + rA) * 128) + colb;
                LDMX4(bA, baddr);
                LDMX4(bB, baddr + 2048u);
                MMA16816(c[0][0], af[ks],     bA[0], bA[2]);
                MMA16816(c[0][1], af[ks],     bA[1], bA[3]);
                MMA16816(c[0][2], af[ks],     bB[0], bB[2]);
                MMA16816(c[0][3], af[ks],     bB[1], bB[3]);
                MMA16816(c[1][0], af[ks] + 4, bA[0], bA[2]);
                MMA16816(c[1][1], af[ks] + 4, bA[1], bA[3]);
                MMA16816(c[1][2], af[ks] + 4, bB[0], bB[2]);
                MMA16816(c[1][3], af[ks] + 4, bB[1], bB[3]);
            }

            // Fold into packed bf16x2 running top-3 (3 ops/value vs 5 scalar).
            if (t < NT - 1){
                #pragma unroll
                for (int mf = 0; mf < 2; mf++)
                    #pragma unroll
                    for (int nf = 0; nf < 4; nf++){
                        ins3pb(__floats2bfloat162_rn(c[mf][nf][0], c[mf][nf][1]),
                               p0[mf*2],   p1[mf*2],   p2[mf*2]);
                        ins3pb(__floats2bfloat162_rn(c[mf][nf][2], c[mf][nf][3]),
                               p0[mf*2+1], p1[mf*2+1], p2[mf*2+1]);
                    }
            } else {
                const int rem = M_ - (NT - 1) * MT;   // 29 valid cols in last tile
                #pragma unroll
                for (int nf = 0; nf < 4; nf++){
                    const int col0 = ncol + pass * 32 + nf * 8 + (lane & 3) * 2;
                    const bool v0 = col0     < rem;
                    const bool v1 = col0 + 1 < rem;
                    #pragma unroll
                    for (int mf = 0; mf < 2; mf++){
                        ins3pb(__floats2bfloat162_rn(v0 ? c[mf][nf][0] : -INFINITY,
                                                     v1 ? c[mf][nf][1] : -INFINITY),
                               p0[mf*2],   p1[mf*2],   p2[mf*2]);
                        ins3pb(__floats2bfloat162_rn(v0 ? c[mf][nf][2] : -INFINITY,
                                                     v1 ? c[mf][nf][3] : -INFINITY),
                               p0[mf*2+1], p1[mf*2+1], p2[mf*2+1]);
                    }
                }
            }
        }
        __syncthreads();
        if (t + 2 < NT){
            const u32 dst = sb + ((t & 1) ? 32768u : 16384u);   // buffer just freed
            #pragma unroll
            for (int i = 0; i < 4; i++){
                int j = tid + i * 256;
                CPA16(dst + SW(j * 16), gB + (size_t)(t + 2) * 16384 + (size_t)j * 16);
            }
            CPA_COMMIT();
        }
    }

    // Collapse packed streams -> scalar top-3 per slot.
    float s0[4], s1[4], s2[4];
    #pragma unroll
    for (int s = 0; s < 4; s++){
        s0[s] = -INFINITY; s1[s] = -INFINITY; s2[s] = -INFINITY;
        float2 a;
        a = __bfloat1622float2(p0[s]); ins3(a.x, s0[s], s1[s], s2[s]); ins3(a.y, s0[s], s1[s], s2[s]);
        a = __bfloat1622float2(p1[s]); ins3(a.x, s0[s], s1[s], s2[s]); ins3(a.y, s0[s], s1[s], s2[s]);
        a = __bfloat1622float2(p2[s]); ins3(a.x, s0[s], s1[s], s2[s]); ins3(a.y, s0[s], s1[s], s2[s]);
    }
    // Merge across the 4 lanes sharing each row.
    #pragma unroll
    for (int off = 1; off <= 2; off <<= 1){
        #pragma unroll
        for (int s = 0; s < 4; s++){
            float u0 = __shfl_xor_sync(0xffffffffu, s0[s], off);
            float u1 = __shfl_xor_sync(0xffffffffu, s1[s], off);
            float u2 = __shfl_xor_sync(0xffffffffu, s2[s], off);
            ins3(u0, s0[s], s1[s], s2[s]);
            ins3(u1, s0[s], s1[s], s2[s]);
            ins3(u2, s0[s], s1[s], s2[s]);
        }
    }
    // Merge the two column-half warps via smem (A region is dead now).
    float* mrg  = reinterpret_cast<float*>(smem);            // 384 floats
    float* rsum = reinterpret_cast<float*>(smem + 2048);     // 128 floats
    if (wid >= 4 && (lane & 3) == 0){
        #pragma unroll
        for (int s = 0; s < 4; s++){
            int row = mrow + (s >> 1) * 16 + (s & 1) * 8 + (lane >> 2);
            mrg[row * 3 + 0] = s0[s];
            mrg[row * 3 + 1] = s1[s];
            mrg[row * 3 + 2] = s2[s];
        }
    }
    __syncthreads();
    if (wid < 4 && (lane & 3) == 0){
        #pragma unroll
        for (int s = 0; s < 4; s++){
            int row = mrow + (s >> 1) * 16 + (s & 1) * 8 + (lane >> 2);
            ins3(mrg[row * 3 + 0], s0[s], s1[s], s2[s]);
            ins3(mrg[row * 3 + 1], s0[s], s1[s], s2[s]);
            ins3(mrg[row * 3 + 2], s0[s], s1[s], s2[s]);
            rsum[row] = s0[s] + s1[s] + s2[s];   // padded rows naturally give 0
        }
    }
    __syncthreads();
    // Block reduction split by batch-image boundary (<=1 boundary: 441 > 128).
    if (wid == 0){
        const int b0    = row0 / HW;
        const int split = (b0 + 1) * HW - row0;   // may be >= 128 (no boundary)
        float lo = 0.f, hi = 0.f;
        #pragma unroll
        for (int i = 0; i < 4; i++){
            int r = lane + 32 * i;
            float v = rsum[r];
            if (r < split) lo += v; else hi += v;
        }
        #pragma unroll
        for (int o = 16; o; o >>= 1){
            lo += __shfl_down_sync(0xffffffffu, lo, o);
            hi += __shfl_down_sync(0xffffffffu, hi, o);
        }
        if (lane == 0){
            g_part[(n * RB + blk) * 2 + 0] = lo;
            g_part[(n * RB + blk) * 2 + 1] = hi;   // belongs to b0+1 (dropped if 16)
        }
    }
}

// ---------------------------------------------------------------------------
// out[b][n] = sum of partials mapping to b. One block, 160 threads.
// ---------------------------------------------------------------------------
__global__ void reduce_out_kernel(float* __restrict__ out){
    const int tid = threadIdx.x;
    if (tid >= B_ * NCLS) return;
    const int b = tid / NCLS;
    const int n = tid % NCLS;
    float s = 0.f;
    #pragma unroll 8
    for (int blk = 0; blk < RB; blk++){
        int b0 = (blk * RT) / HW;
        float v0 = g_part[(n * RB + blk) * 2 + 0];
        float v1 = g_part[(n * RB + blk) * 2 + 1];
        if (b0 == b)     s += v0;
        if (b0 + 1 == b) s += v1;
    }
    out[tid] = s;
}

extern "C" void kernel_launch(void* const* d_in, const int* in_sizes, int n_in,
                              void* d_out, int out_size){
    const float* x1 = (const float*)d_in[0];   // [16,64,21,21] fp32
    const float* x2 = (const float*)d_in[1];   // [10,64,2205]  fp32
    float* out = (float*)d_out;                // [16,10] fp32

    norm_kernel<<<QB + SBK, 256>>>(x1, x2);
    sim_mma_kernel<<<dim3(RB, NCLS), 256>>>();
    reduce_out_kernel<<<1, 192>>>(out);
}